// round 16
// baseline (speedup 1.0000x reference)
#include <cuda_runtime.h>
#include <cuda_fp16.h>
#include <math.h>
#include <stdint.h>

#define Bb 32
#define Ss 512
#define NNODE 6
#define CIN 12
#define H1C 128
#define HHC 256
#define TCC 1536
#define LLEN 512
#define LROWS 544           /* 16 pad | 512 | 16 pad rows in [l][c] layout */
#define M1R (Bb*Ss*NNODE)   /* 98304 */
#define NBS (Bb*Ss)         /* 16384 */
#define RKK (5*TCC)         /* 7680  */
#define BNEPS 1e-5f

// stat regions (disjoint, zeroed once)
#define ST1 0
#define ST2 512
#define STC1 1536
#define STC2 4608
#define STTOT 7680

// ---------------- scratch (device globals; no runtime allocation) ----------
__device__ float  g_xc1 [M1R*H1C];
__device__ float  g_res1[M1R*H1C];
__device__ __half g_h1H [M1R*H1C];     // fp16 at write (BN1 output)
__device__ float  g_y2  [M1R*HHC];
__device__ float  g_res2[M1R*HHC];
__device__ float  g_xc2 [M1R*HHC];
__device__ __half g_htH [Bb*LROWS*TCC];  // [l][c] fp16, padded rows
__device__ __half g_t1H [Bb*LROWS*TCC];
__device__ __half g_t2H [Bb*LROWS*TCC];
__device__ __half g_wt1H[RKK*TCC];       // fragment-permuted fp16 tiles
__device__ __half g_wt2H[RKK*TCC];
__device__ __half g_wBH [H1C*512];       // fragment-permuted (w2|rw2) fp16 tiles
__device__ float  g_biasP[512];
__device__ __half g_owRH[TCC*HHC];       // fragment-permuted ow fp16 tiles
__device__ float  g_stats[STTOT];

// ---------------- helpers ----------------------------------------------------
__device__ __forceinline__ unsigned f2tf32(float f) {
    unsigned u; asm("cvt.rna.tf32.f32 %0, %1;" : "=r"(u) : "f"(f)); return u;
}
#define MMA_F16(c, a, b) \
    asm volatile("mma.sync.aligned.m16n8k16.row.col.f32.f16.f16.f32 " \
        "{%0,%1,%2,%3}, {%4,%5,%6,%7}, {%8,%9}, {%0,%1,%2,%3};" \
        : "+f"((c)[0]), "+f"((c)[1]), "+f"((c)[2]), "+f"((c)[3]) \
        : "r"((a)[0]), "r"((a)[1]), "r"((a)[2]), "r"((a)[3]), \
          "r"((b)[0]), "r"((b)[1]))

__device__ __forceinline__ void cpasync16(uint32_t dst, const void* src) {
    asm volatile("cp.async.cg.shared.global [%0], [%1], 16;" :: "r"(dst), "l"(src));
}
__device__ __forceinline__ void cpa_commit() {
    asm volatile("cp.async.commit_group;" ::: "memory");
}
template<int N>
__device__ __forceinline__ void cpa_wait() {
    asm volatile("cp.async.wait_group %0;" :: "n"(N) : "memory");
}
__device__ __forceinline__ uint32_t s2u(const void* p) {
    return (uint32_t)__cvta_generic_to_shared(p);
}
__device__ __forceinline__ unsigned packh2(float a, float b) {
    __half2 h = __floats2half2_rn(a, b);
    return *(unsigned*)&h;
}

// ---------------- merged prep kernel ----------------------------------------
// [0,30) zero stats | [30,798) zero pads | [798,830) pack gcn2 fp16 tiles
// | [830,832) bias pack | [832,1024) pack_ow fp16 tiles
__global__ void prep_all(const float* __restrict__ w2, const float* __restrict__ rw2,
                         const float* __restrict__ b2, const float* __restrict__ rb2,
                         const float* __restrict__ ow) {
    int blk = blockIdx.x;
    int tid = threadIdx.x;
    if (blk < 30) {
        int i = blk * 256 + tid;
        if (i < STTOT) g_stats[i] = 0.f;
        return;
    }
    if (blk < 798) {
        int idx = (blk - 30) * 256 + tid;
        const int per = Bb * 32 * (TCC/8);
        if (idx >= per) return;
        int col8 = idx % (TCC/8);
        int rr   = (idx / (TCC/8)) % 32;
        int b    = idx / (32 * (TCC/8));
        int row  = rr < 16 ? rr : 512 + rr;
        size_t off = ((size_t)b * LROWS + row) * TCC + col8 * 8;
        uint4 z = make_uint4(0,0,0,0);
        *(uint4*)((char*)g_htH + off*2) = z;
        *(uint4*)((char*)g_t1H + off*2) = z;
        return;
    }
    if (blk < 830) {
        int tile = blk - 798;                 // tk*4 + cb ; tk in [0,8), cb in [0,4)
        int tk = tile >> 2, cb = tile & 3;
        unsigned* dst = (unsigned*)g_wBH + (size_t)tile * 1024 + tid * 4;
#pragma unroll
        for (int u = 0; u < 4; u++) {
            int pos = tid * 4 + u;
            int r = pos & 3, lane = (pos >> 2) & 31, mi = pos >> 7;
            int kl = 2 * (lane & 3) + ((r >> 1) << 3);
            int ml = mi * 16 + (lane >> 2) + ((r & 1) << 3);
            int k = tk * 16 + kl;
            int o = cb * 128 + ml;
            const float* src = (o < 256) ? (w2 + (size_t)o * H1C)
                                         : (rw2 + (size_t)(o - 256) * H1C);
            dst[u] = packh2(src[k], src[k + 1]);
        }
        return;
    }
    if (blk < 832) {
        int half = blk - 830;
        g_biasP[half * 256 + tid] = half ? rb2[tid] : b2[tid];
        return;
    }
    {
        int tile = blk - 832;                 // 0..191 : tk*2 + cb
        int tk = tile >> 1, cb = tile & 1;
        unsigned* dst = (unsigned*)g_owRH + (size_t)tile * 1024 + tid * 4;
#pragma unroll
        for (int u = 0; u < 4; u++) {
            int pos = tid * 4 + u;
            int r = pos & 3, lane = (pos >> 2) & 31, mi = pos >> 7;
            int kl = 2 * (lane & 3) + ((r >> 1) << 3);
            int ml = mi * 16 + (lane >> 2) + ((r & 1) << 3);
            int c = tk * 16 + kl;
            int o = cb * 128 + ml;
            float f0 = ow[(size_t)o * TCC + c];
            float f1 = ow[(size_t)o * TCC + c + 1];
            dst[u] = packh2(f0, f1);
        }
    }
}

// coalesced conv-weight transform -> fragment-permuted fp16 tiles
__global__ void wtrans_convH2(const float* __restrict__ cw, __half* __restrict__ wt) {
    __shared__ float sm[128 * 81];
    int blk = blockIdx.x;                 // cib*12 + cb ; cib in [0,96)
    int cib = blk / 12, cb = blk % 12;
    int ci0 = cib * 16;
    int tid = threadIdx.x;
    for (int i = tid; i < 128 * 80; i += 256) {
        int co = i / 80, j = i % 80;
        sm[co * 81 + j] = cw[((size_t)(cb * 128 + co) * TCC + ci0) * 5 + j];
    }
    __syncthreads();
#pragma unroll
    for (int k = 0; k < 5; k++) {
        int tile = (k * 96 + cib) * 12 + cb;
        unsigned* dst = (unsigned*)wt + (size_t)tile * 1024 + tid * 4;
#pragma unroll
        for (int u = 0; u < 4; u++) {
            int pos = tid * 4 + u;
            int r = pos & 3, lane = (pos >> 2) & 31, mi = pos >> 7;
            int kl = 2 * (lane & 3) + ((r >> 1) << 3);
            int ml = mi * 16 + (lane >> 2) + ((r & 1) << 3);
            float f0 = sm[ml * 81 + kl * 5 + k];
            float f1 = sm[ml * 81 + (kl + 1) * 5 + k];
            dst[u] = packh2(f0, f1);
        }
    }
}

// ======== GCN stage 1: register node-mix + fused BN1 stats ==================
#define G1BS 16
__global__ __launch_bounds__(256) void gcn1_fused(
        const float* __restrict__ x, const float* __restrict__ adj,
        const float* __restrict__ eimp,
        const float* __restrict__ w1, const float* __restrict__ b1,
        const float* __restrict__ rw1, const float* __restrict__ rb1) {
    __shared__ float xs[G1BS * NNODE * CIN];
    __shared__ float Asm[NNODE * NNODE];
    const int tid = threadIdx.x;
    const int blk = blockIdx.x;
    const int path = tid >> 7;        // 0: res, 1: xc
    const int c = tid & 127;

    for (int i = tid; i < G1BS * NNODE * CIN; i += 256)
        xs[i] = x[(size_t)blk * (G1BS * NNODE * CIN) + i];
    if (tid < NNODE * NNODE) Asm[tid] = adj[tid] * eimp[tid];

    float wrow[CIN];
    const float* wsrc = path ? (w1 + c * CIN) : (rw1 + c * CIN);
#pragma unroll
    for (int i = 0; i < CIN; i++) wrow[i] = wsrc[i];
    const float bias = path ? b1[c] : rb1[c];
    __syncthreads();

    float ssum = 0.f, sqq = 0.f;
    for (int j = 0; j < G1BS; j++) {
        const float* xj = xs + j * (NNODE * CIN);
        float v[NNODE];
#pragma unroll
        for (int n = 0; n < NNODE; n++) {
            float acc = bias;
#pragma unroll
            for (int i = 0; i < CIN; i++) acc += wrow[i] * xj[n * CIN + i];
            v[n] = acc;
        }
        const size_t base = ((size_t)(blk * G1BS + j) * NNODE) * H1C + c;
        if (path) {
#pragma unroll
            for (int n = 0; n < NNODE; n++) {
                float m = 0.f;
#pragma unroll
                for (int q = 0; q < NNODE; q++) m += Asm[n * NNODE + q] * v[q];
                g_xc1[base + (size_t)n * H1C] = m;
                ssum += m; sqq += m * m;
            }
        } else {
#pragma unroll
            for (int n = 0; n < NNODE; n++) {
                g_res1[base + (size_t)n * H1C] = v[n];
                ssum += v[n]; sqq += v[n] * v[n];
            }
        }
    }
    float* st = g_stats + ST1 + (path ? 0 : 2 * H1C);
    atomicAdd(&st[c],        ssum);
    atomicAdd(&st[H1C + c],  sqq);
}

__global__ void bn_apply1(const float* __restrict__ g1, const float* __restrict__ beta1,
                          const float* __restrict__ rg1, const float* __restrict__ rbeta1) {
    size_t idx = (size_t)blockIdx.x * blockDim.x + threadIdx.x;
    if (idx >= (size_t)M1R*H1C) return;
    int c = (int)(idx % H1C);
    const float* st = g_stats + ST1;
    const float invM = 1.f / (float)M1R;
    float m1 = st[c] * invM;
    float v1 = st[H1C + c] * invM - m1*m1;
    float m2 = st[2*H1C + c] * invM;
    float v2 = st[3*H1C + c] * invM - m2*m2;
    float a = (g_xc1[idx]  - m1) * rsqrtf(v1 + BNEPS) * g1[c]  + beta1[c];
    float r = (g_res1[idx] - m2) * rsqrtf(v2 + BNEPS) * rg1[c] + rbeta1[c];
    float o = a + r;
    o = o > 0.f ? o : 0.f;
    g_h1H[idx] = __float2half(o);
}

// ======== gcn2 dual GEMM (fp16 mma) + fused res2 stats =======================
#define ASZh 4096
#define BROWB 48
#define BSZh (128*BROWB)
#define STGOh (ASZh + BSZh)

__global__ __launch_bounds__(256, 2) void gcn2_gemm_f16() {
    extern __shared__ __align__(128) char dsm[];
    const int tid = threadIdx.x;
    const int cb = blockIdx.x;           // 0..3 : channel block (0,1 y2 | 2,3 res2)
    const int bm = cb * 128;
    const int bn = blockIdx.y * 128;     // row block
    const int lane = tid & 31, wid = tid >> 5;
    const int wm = (wid & 1) * 64, wn = (wid >> 1) * 32;
    const int g = lane >> 2, tg = lane & 3;
    const int aoff = (wid & 1) * 4;
    const uint32_t smem_u = s2u(dsm);

    float acc[4][4][4];
#pragma unroll
    for (int mi = 0; mi < 4; mi++)
#pragma unroll
        for (int ni = 0; ni < 4; ni++)
#pragma unroll
            for (int r = 0; r < 4; r++) acc[mi][ni][r] = 0.f;

    const int NT = H1C / 16;   // 8
    const int brow = tid >> 1, bhalf = tid & 1;

    auto load_stage = [&](int slot, int t) {
        const uint32_t sa = smem_u + slot * STGOh;
        const uint32_t sb = sa + ASZh;
        cpasync16(sa + tid * 16, g_wBH + ((size_t)t * 4 + cb) * 2048 + tid * 8);
        const __half* src = g_h1H + (size_t)(bn + brow) * H1C + t * 16 + bhalf * 8;
        cpasync16(sb + brow * BROWB + bhalf * 16, src);
    };
    load_stage(0, 0); cpa_commit();
    load_stage(1, 1); cpa_commit();

    for (int t = 0; t < NT; ++t) {
        cpa_wait<1>();
        __syncthreads();
        if (t + 2 < NT) load_stage((t + 2) % 3, t + 2);
        cpa_commit();
        const int cur = t % 3;
        const uint4* Af = (const uint4*)(dsm + cur * STGOh);
        const char* Bs = dsm + cur * STGOh + ASZh;

        unsigned a[4][4], b[4][2];
#pragma unroll
        for (int mi = 0; mi < 4; mi++) {
            uint4 v = Af[(aoff + mi) * 32 + lane];
            a[mi][0] = v.x; a[mi][1] = v.y; a[mi][2] = v.z; a[mi][3] = v.w;
        }
#pragma unroll
        for (int ni = 0; ni < 4; ni++) {
            int row = wn + ni * 8 + g;
            b[ni][0] = *(const unsigned*)(Bs + row * BROWB + tg * 4);
            b[ni][1] = *(const unsigned*)(Bs + row * BROWB + 16 + tg * 4);
        }
#pragma unroll
        for (int mi = 0; mi < 4; mi++)
#pragma unroll
            for (int ni = 0; ni < 4; ni++)
                MMA_F16(acc[mi][ni], a[mi], b[ni]);
    }

    float* tgt = (cb < 2) ? g_y2 : g_res2;
    const int cbase = (cb & 1) * 128;
    float* st = g_stats + ST2;
#pragma unroll
    for (int mi = 0; mi < 4; mi++) {
        int o0 = bm + wm + mi * 16 + g;
        int col = cbase + wm + mi * 16 + g;
        float bo0 = g_biasP[o0], bo1 = g_biasP[o0 + 8];
        float s0 = 0.f, q0 = 0.f, s1 = 0.f, q1 = 0.f;
#pragma unroll
        for (int ni = 0; ni < 4; ni++) {
            int m0 = bn + wn + ni * 8 + 2 * tg;
            float v0 = acc[mi][ni][0] + bo0;
            float v1 = acc[mi][ni][1] + bo0;
            float v2 = acc[mi][ni][2] + bo1;
            float v3 = acc[mi][ni][3] + bo1;
            tgt[(size_t)m0 * HHC + col]           = v0;
            tgt[(size_t)(m0 + 1) * HHC + col]     = v1;
            tgt[(size_t)m0 * HHC + col + 8]       = v2;
            tgt[(size_t)(m0 + 1) * HHC + col + 8] = v3;
            s0 += v0 + v1; q0 += v0*v0 + v1*v1;
            s1 += v2 + v3; q1 += v2*v2 + v3*v3;
        }
        if (cb >= 2) {      // res2 stats fused
            s0 += __shfl_xor_sync(0xffffffffu, s0, 1);
            s0 += __shfl_xor_sync(0xffffffffu, s0, 2);
            q0 += __shfl_xor_sync(0xffffffffu, q0, 1);
            q0 += __shfl_xor_sync(0xffffffffu, q0, 2);
            s1 += __shfl_xor_sync(0xffffffffu, s1, 1);
            s1 += __shfl_xor_sync(0xffffffffu, s1, 2);
            q1 += __shfl_xor_sync(0xffffffffu, q1, 1);
            q1 += __shfl_xor_sync(0xffffffffu, q1, 2);
            if (tg == 0) {
                atomicAdd(&st[2*HHC + col],     s0);
                atomicAdd(&st[3*HHC + col],     q0);
                atomicAdd(&st[2*HHC + col + 8], s1);
                atomicAdd(&st[3*HHC + col + 8], q1);
            }
        }
    }
}

// ---------------- node mix stage 2 + fused xc2 stats -------------------------
__global__ void nodemix2(const float* __restrict__ adj, const float* __restrict__ eimp) {
    __shared__ float ys[NNODE*HHC];
    __shared__ float Asm[NNODE*NNODE];
    int bs = blockIdx.x, tid = threadIdx.x;
    if (tid < NNODE*NNODE) Asm[tid] = adj[tid] * eimp[tid];
    for (int e = tid; e < NNODE*HHC; e += blockDim.x)
        ys[e] = g_y2[(size_t)bs*NNODE*HHC + e];
    __syncthreads();
    float ssum = 0.f, sqq = 0.f;
    for (int e = tid; e < NNODE*HHC; e += blockDim.x) {
        int n = e / HHC, c = e % HHC;
        float acc = 0.f;
#pragma unroll
        for (int m = 0; m < NNODE; m++) acc += Asm[n*NNODE + m] * ys[m*HHC + c];
        g_xc2[(size_t)bs*NNODE*HHC + e] = acc;
        ssum += acc; sqq += acc * acc;
    }
    float* st = g_stats + ST2;
    atomicAdd(&st[tid],       ssum);      // c == tid for all iterations
    atomicAdd(&st[HHC + tid], sqq);
}

// ---------------- BN apply stage 2 -> [l][c] fp16 ----------------------------
__global__ void bn_apply2_tohalf(const float* __restrict__ g2, const float* __restrict__ beta2,
                                 const float* __restrict__ rg2, const float* __restrict__ rbeta2) {
    int row = blockIdx.x;        // (b*Ss + s)*6 + n
    int c = threadIdx.x;         // 0..255
    const float* st = g_stats + ST2;
    const float invM = 1.f / (float)M1R;
    float m1 = st[c] * invM;
    float v1 = st[HHC + c] * invM - m1*m1;
    float m2 = st[2*HHC + c] * invM;
    float v2 = st[3*HHC + c] * invM - m2*m2;
    float sc1 = rsqrtf(v1 + BNEPS) * g2[c];
    float sh1 = beta2[c] - m1*sc1;
    float sc2 = rsqrtf(v2 + BNEPS) * rg2[c];
    float sh2 = rbeta2[c] - m2*sc2;
    size_t ridx = (size_t)row * HHC + c;
    float o = g_xc2[ridx]*sc1 + sh1 + g_res2[ridx]*sc2 + sh2;
    o = o > 0.f ? o : 0.f;
    int n = row % NNODE;
    int bs = row / NNODE;
    int b = bs / Ss, s = bs % Ss;
    g_htH[((size_t)b * LROWS + 16 + s) * TCC + n * HHC + c] = __float2half(o);
}

// ======================= conv1d fp16 mma GEMM, ci-tiled, 4-stage =============
#define A5SZ 20480          /* 5 x 4096 weight tap tiles */
#define BROWB2 48           /* B smem row stride bytes */
#define STG3 26880          /* A5SZ + 132*48 = 26816, padded to 128 */
#define CST3 4

__global__ __launch_bounds__(256, 2) void conv_gemm_f16(
        const __half* __restrict__ X, const __half* __restrict__ Wt,
        __half* __restrict__ Y, float* __restrict__ statsB) {
    extern __shared__ __align__(128) char dsm[];
    const int tid = threadIdx.x;
    const int cb = blockIdx.x;
    const int bm = cb * 128;           // co
    const int bn = blockIdx.y * 128;   // l
    const __half* Xb = X + (size_t)blockIdx.z * LROWS * TCC;
    __half* Yb = Y + (size_t)blockIdx.z * LROWS * TCC;
    const int lane = tid & 31, wid = tid >> 5;
    const int wm = (wid & 1) * 64, wn = (wid >> 1) * 32;
    const int g = lane >> 2, tg = lane & 3;
    const int aoff = (wid & 1) * 4;
    const uint32_t smem_u = s2u(dsm);

    float acc[4][4][4];
#pragma unroll
    for (int mi = 0; mi < 4; mi++)
#pragma unroll
        for (int ni = 0; ni < 4; ni++)
#pragma unroll
            for (int r = 0; r < 4; r++) acc[mi][ni][r] = 0.f;

    const int NTC = TCC / 16;   // 96 ci-tiles

    auto load_stage = [&](int slot, int it) {
        const int ci0 = it * 16;
        const uint32_t sa = smem_u + slot * STG3;
        const uint32_t sb = sa + A5SZ;
#pragma unroll
        for (int k = 0; k < 5; k++)
            cpasync16(sa + k * 4096 + tid * 16,
                      Wt + ((size_t)(k * 96 + it) * 12 + cb) * 2048 + tid * 8);
        for (int i = tid; i < 264; i += 256) {
            int r = i >> 1, h = i & 1;
            cpasync16(sb + r * BROWB2 + h * 16,
                      Xb + (size_t)(14 + bn + r) * TCC + ci0 + h * 8);
        }
    };

    load_stage(0, 0); cpa_commit();
    load_stage(1, 1); cpa_commit();
    load_stage(2, 2); cpa_commit();

    for (int t = 0; t < NTC; ++t) {
        cpa_wait<2>();
        __syncthreads();
        if (t + 3 < NTC) load_stage((t + 3) % CST3, t + 3);
        cpa_commit();

        const char* base = dsm + (t % CST3) * STG3;
        const char* Bs = base + A5SZ;
#pragma unroll
        for (int k = 0; k < 5; k++) {
            const uint4* Af = (const uint4*)(base + k * 4096);
            unsigned a[4][4], b[4][2];
#pragma unroll
            for (int mi = 0; mi < 4; mi++) {
                uint4 v = Af[(aoff + mi) * 32 + lane];
                a[mi][0] = v.x; a[mi][1] = v.y; a[mi][2] = v.z; a[mi][3] = v.w;
            }
#pragma unroll
            for (int ni = 0; ni < 4; ni++) {
                int row = wn + ni * 8 + g + k;
                b[ni][0] = *(const unsigned*)(Bs + row * BROWB2 + tg * 4);
                b[ni][1] = *(const unsigned*)(Bs + row * BROWB2 + 16 + tg * 4);
            }
#pragma unroll
            for (int mi = 0; mi < 4; mi++)
#pragma unroll
                for (int ni = 0; ni < 4; ni++)
                    MMA_F16(acc[mi][ni], a[mi], b[ni]);
        }
    }

    // epilogue: store fp16 [l][c] + fused per-channel stats from fp32 accs
#pragma unroll
    for (int mi = 0; mi < 4; mi++) {
        int m0 = bm + wm + mi * 16 + g;
        float s0 = 0.f, q0 = 0.f, s1 = 0.f, q1 = 0.f;
#pragma unroll
        for (int ni = 0; ni < 4; ni++) {
            float v0 = acc[mi][ni][0], v1 = acc[mi][ni][1];
            float v2 = acc[mi][ni][2], v3 = acc[mi][ni][3];
            s0 += v0 + v1; q0 += v0*v0 + v1*v1;
            s1 += v2 + v3; q1 += v2*v2 + v3*v3;
            int l0 = bn + wn + ni * 8 + 2 * tg;
            size_t r0 = ((size_t)(16 + l0)) * TCC;
            size_t r1 = ((size_t)(17 + l0)) * TCC;
            Yb[r0 + m0]     = __float2half(v0);
            Yb[r1 + m0]     = __float2half(v1);
            Yb[r0 + m0 + 8] = __float2half(v2);
            Yb[r1 + m0 + 8] = __float2half(v3);
        }
        s0 += __shfl_xor_sync(0xffffffffu, s0, 1);
        s0 += __shfl_xor_sync(0xffffffffu, s0, 2);
        q0 += __shfl_xor_sync(0xffffffffu, q0, 1);
        q0 += __shfl_xor_sync(0xffffffffu, q0, 2);
        s1 += __shfl_xor_sync(0xffffffffu, s1, 1);
        s1 += __shfl_xor_sync(0xffffffffu, s1, 2);
        q1 += __shfl_xor_sync(0xffffffffu, q1, 1);
        q1 += __shfl_xor_sync(0xffffffffu, q1, 2);
        if (tg == 0) {
            atomicAdd(&statsB[m0],         s0);
            atomicAdd(&statsB[TCC + m0],   q0);
            atomicAdd(&statsB[m0 + 8],     s1);
            atomicAdd(&statsB[TCC + m0+8], q1);
        }
    }
}

// ---------------- conv BN apply in-place on fp16 [l][c] ----------------------
__global__ void conv_bnH(__half* __restrict__ T, const float* __restrict__ g,
                         const float* __restrict__ beta, const __half* __restrict__ resid,
                         const float* __restrict__ statsB) {
    size_t idx = (size_t)blockIdx.x * blockDim.x + threadIdx.x;
    const size_t total = (size_t)Bb * LLEN * (TCC/2);
    if (idx >= total) return;
    int c2  = (int)(idx % (TCC/2));
    int l   = (int)((idx / (TCC/2)) % LLEN);
    int b   = (int)(idx / ((size_t)(TCC/2) * LLEN));
    int c   = c2 * 2;
    size_t a = ((size_t)b * LROWS + 16 + l) * TCC + c;
    const float invM = 1.f / (float)(Bb * LLEN);
    float m0 = statsB[c] * invM;
    float va = statsB[TCC + c] * invM - m0*m0;
    float m1 = statsB[c+1] * invM;
    float vb = statsB[TCC + c+1] * invM - m1*m1;
    __half2 hv = *(__half2*)(T + a);
    float2 f = __half22float2(hv);
    float o0 = (f.x - m0) * rsqrtf(va + BNEPS) * g[c]   + beta[c];
    float o1 = (f.y - m1) * rsqrtf(vb + BNEPS) * g[c+1] + beta[c+1];
    o0 = o0 > 0.f ? o0 : 0.f;
    o1 = o1 > 0.f ? o1 : 0.f;
    if (resid) {
        float2 r = __half22float2(*(const __half2*)(resid + a));
        o0 += r.x; o1 += r.y;
    }
    *(__half2*)(T + a) = __floats2half2_rn(o0, o1);
}

// ======================= output GEMM (fp16 mma, permuted A) =================
__global__ __launch_bounds__(256, 2) void out_gemm_f16(
        const __half* __restrict__ T2, const float* __restrict__ OB,
        float* __restrict__ OUT) {
    extern __shared__ __align__(128) char dsm[];
    const int tid = threadIdx.x;
    const int cb = blockIdx.x;
    const int bm = cb * 128;           // o
    const int bn = blockIdx.y * 128;   // s
    const int b  = blockIdx.z;
    const __half* T2b = T2 + (size_t)b * LROWS * TCC;
    const int lane = tid & 31, wid = tid >> 5;
    const int wm = (wid & 1) * 64, wn = (wid >> 1) * 32;
    const int g = lane >> 2, tg = lane & 3;
    const int aoff = (wid & 1) * 4;
    const uint32_t smem_u = s2u(dsm);

    float acc[4][4][4];
#pragma unroll
    for (int mi = 0; mi < 4; mi++)
#pragma unroll
        for (int ni = 0; ni < 4; ni++)
#pragma unroll
            for (int r = 0; r < 4; r++) acc[mi][ni][r] = 0.f;

    const int NT = TCC / 16;   // 96
    const int brow = tid >> 1, bhalf = tid & 1;

    auto load_stage = [&](int slot, int t) {
        const uint32_t sa = smem_u + slot * STGOh;
        const uint32_t sb = sa + ASZh;
        cpasync16(sa + tid * 16, g_owRH + ((size_t)t * 2 + cb) * 2048 + tid * 8);
        const __half* src = T2b + (size_t)(16 + bn + brow) * TCC + t * 16 + bhalf * 8;
        cpasync16(sb + brow * BROWB + bhalf * 16, src);
    };
    load_stage(0, 0); cpa_commit();
    load_stage(1, 1); cpa_commit();

    for (int t = 0; t < NT; ++t) {
        cpa_wait<1>();
        __syncthreads();
        if (t + 2 < NT) load_stage((t + 2) % 3, t + 2);
        cpa_commit();
        const int cur = t % 3;
        const uint4* Af = (const uint4*)(dsm + cur * STGOh);
        const char* Bs = dsm + cur * STGOh + ASZh;

        unsigned a[4][4], b[4][2];
#pragma unroll
        for (int mi = 0; mi < 4; mi++) {
            uint4 v = Af[(aoff + mi) * 32 + lane];
            a[mi][0] = v.x; a[mi][1] = v.y; a[mi][2] = v.z; a[mi][3] = v.w;
        }
#pragma unroll
        for (int ni = 0; ni < 4; ni++) {
            int row = wn + ni * 8 + g;
            b[ni][0] = *(const unsigned*)(Bs + row * BROWB + tg * 4);
            b[ni][1] = *(const unsigned*)(Bs + row * BROWB + 16 + tg * 4);
        }
#pragma unroll
        for (int mi = 0; mi < 4; mi++)
#pragma unroll
            for (int ni = 0; ni < 4; ni++)
                MMA_F16(acc[mi][ni], a[mi], b[ni]);
    }

#pragma unroll
    for (int mi = 0; mi < 4; mi++) {
        int o0 = bm + wm + mi * 16 + g;
        float bo0 = OB[o0], bo1 = OB[o0 + 8];
#pragma unroll
        for (int ni = 0; ni < 4; ni++) {
            int sL = bn + wn + ni * 8 + 2 * tg;
            float v0 = acc[mi][ni][0] + bo0; v0 = v0 > 0.f ? v0 : 0.f;
            float v1 = acc[mi][ni][1] + bo0; v1 = v1 > 0.f ? v1 : 0.f;
            float v2 = acc[mi][ni][2] + bo1; v2 = v2 > 0.f ? v2 : 0.f;
            float v3 = acc[mi][ni][3] + bo1; v3 = v3 > 0.f ? v3 : 0.f;
            OUT[((size_t)b * Ss + sL    ) * HHC + o0    ] = v0;
            OUT[((size_t)b * Ss + sL + 1) * HHC + o0    ] = v1;
            OUT[((size_t)b * Ss + sL    ) * HHC + o0 + 8] = v2;
            OUT[((size_t)b * Ss + sL + 1) * HHC + o0 + 8] = v3;
        }
    }
}

// ---------------- launch ----------------------------------------------------
extern "C" void kernel_launch(void* const* d_in, const int* in_sizes, int n_in,
                              void* d_out, int out_size) {
    const float* x     = (const float*)d_in[0];
    const float* adj   = (const float*)d_in[1];
    const float* eimp  = (const float*)d_in[2];
    const float* w1    = (const float*)d_in[3];
    const float* b1    = (const float*)d_in[4];
    const float* rw1   = (const float*)d_in[5];
    const float* rb1   = (const float*)d_in[6];
    const float* rg1   = (const float*)d_in[7];
    const float* rbeta1= (const float*)d_in[8];
    const float* g1    = (const float*)d_in[9];
    const float* beta1 = (const float*)d_in[10];
    const float* w2    = (const float*)d_in[11];
    const float* b2    = (const float*)d_in[12];
    const float* rw2   = (const float*)d_in[13];
    const float* rb2   = (const float*)d_in[14];
    const float* rg2   = (const float*)d_in[15];
    const float* rbeta2= (const float*)d_in[16];
    const float* g2    = (const float*)d_in[17];
    const float* beta2 = (const float*)d_in[18];
    const float* cw1   = (const float*)d_in[19];
    /* cb1 = d_in[20]: cancels exactly through BN mean-subtraction */
    const float* cg1   = (const float*)d_in[21];
    const float* cbeta1= (const float*)d_in[22];
    const float* cw2   = (const float*)d_in[23];
    /* cb2 = d_in[24]: cancels exactly */
    const float* cg2   = (const float*)d_in[25];
    const float* cbeta2= (const float*)d_in[26];
    const float* ow    = (const float*)d_in[27];
    const float* ob    = (const float*)d_in[28];
    float* out = (float*)d_out;

    float *p_stats;
    __half *p_htH, *p_t1H, *p_t2H, *p_wt1H, *p_wt2H;
    cudaGetSymbolAddress((void**)&p_stats, g_stats);
    cudaGetSymbolAddress((void**)&p_htH,  g_htH);
    cudaGetSymbolAddress((void**)&p_t1H,  g_t1H);
    cudaGetSymbolAddress((void**)&p_t2H,  g_t2H);
    cudaGetSymbolAddress((void**)&p_wt1H, g_wt1H);
    cudaGetSymbolAddress((void**)&p_wt2H, g_wt2H);

    cudaFuncSetAttribute(conv_gemm_f16,
                         cudaFuncAttributeMaxDynamicSharedMemorySize, CST3 * STG3);
    cudaFuncSetAttribute(gcn2_gemm_f16,
                         cudaFuncAttributeMaxDynamicSharedMemorySize, 3 * STGOh);
    cudaFuncSetAttribute(out_gemm_f16,
                         cudaFuncAttributeMaxDynamicSharedMemorySize, 3 * STGOh);

    // -------- prep: merged zero/pack + weight transforms --------------------
    prep_all<<<1024, 256>>>(w2, rw2, b2, rb2, ow);
    wtrans_convH2<<<96*12, 256>>>(cw1, p_wt1H);
    wtrans_convH2<<<96*12, 256>>>(cw2, p_wt2H);

    // -------- GCN stage 1 (fused linear + register node-mix + stats) --------
    gcn1_fused<<<NBS/G1BS, 256>>>(x, adj, eimp, w1, b1, rw1, rb1);
    bn_apply1<<<(M1R*H1C)/256, 256>>>(g1, beta1, rg1, rbeta1);

    // -------- GCN stage 2 (fp16 dual GEMM, res2 stats fused) --------
    gcn2_gemm_f16<<<dim3(4, M1R/128), 256, 3*STGOh>>>();
    nodemix2<<<NBS, 256>>>(adj, eimp);     // xc2 stats fused
    bn_apply2_tohalf<<<M1R, 256>>>(g2, beta2, rg2, rbeta2);

    // -------- TCN conv 1 (fp16 mma, ci-tiled, 4-stage) --------
    conv_gemm_f16<<<dim3(TCC/128, LLEN/128, Bb), 256, CST3*STG3>>>(
        p_htH, p_wt1H, p_t1H, p_stats + STC1);
    conv_bnH<<<(Bb*LLEN*(TCC/2) + 255)/256, 256>>>(
        p_t1H, cg1, cbeta1, (const __half*)nullptr, p_stats + STC1);

    // -------- TCN conv 2 + residual --------
    conv_gemm_f16<<<dim3(TCC/128, LLEN/128, Bb), 256, CST3*STG3>>>(
        p_t1H, p_wt2H, p_t2H, p_stats + STC2);
    conv_bnH<<<(Bb*LLEN*(TCC/2) + 255)/256, 256>>>(
        p_t2H, cg2, cbeta2, p_htH, p_stats + STC2);

    // -------- output layer (fp16 mma) --------
    out_gemm_f16<<<dim3(HHC/128, LLEN/128, Bb), 256, 3*STGOh>>>(p_t2H, ob, out);

    (void)in_sizes; (void)n_in; (void)out_size;
}